// round 1
// baseline (speedup 1.0000x reference)
#include <cuda_runtime.h>
#include <cuda_bf16.h>
#include <math_constants.h>

// Problem constants
#define BATCH 8
#define NPTS 2500
#define NUM_PATCHES 25
#define PATCH_P 100      // 2500 / 25
#define K_GLOBAL 32
#define K_PATCH 16
#define TOTAL_PTS (BATCH * NPTS)   // 20000

// Scratch: |normal| for global and patch estimates, flat point id = b*2500+i
__device__ float g_absn_global[TOTAL_PTS * 3];
__device__ float g_absn_patch[TOTAL_PTS * 3];

// ---------------------------------------------------------------------------
// 3x3 symmetric eigen-solve: eigenvector of the SMALLEST eigenvalue.
// Double precision for robustness (only 40k calls total). Writes |v|.
// ---------------------------------------------------------------------------
__device__ __forceinline__ void smallest_evec_abs(
    float sxx, float sxy, float sxz, float syy, float syz, float szz,
    float out[3])
{
    double a00 = sxx, a01 = sxy, a02 = sxz;
    double a11 = syy, a12 = syz, a22 = szz;

    double p1 = a01 * a01 + a02 * a02 + a12 * a12;
    double q  = (a00 + a11 + a22) * (1.0 / 3.0);
    double d0 = a00 - q, d1 = a11 - q, d2 = a22 - q;
    double p2 = d0 * d0 + d1 * d1 + d2 * d2 + 2.0 * p1;

    double lam;
    if (p2 <= 1e-300) {
        lam = q;  // (near) multiple of identity — any direction works
    } else {
        double p   = sqrt(p2 * (1.0 / 6.0));
        double inv = 1.0 / p;
        double b00 = d0 * inv, b11 = d1 * inv, b22 = d2 * inv;
        double b01 = a01 * inv, b02 = a02 * inv, b12 = a12 * inv;
        double detB = b00 * (b11 * b22 - b12 * b12)
                    - b01 * (b01 * b22 - b12 * b02)
                    + b02 * (b01 * b12 - b11 * b02);
        double r = 0.5 * detB;
        r = fmin(1.0, fmax(-1.0, r));
        double phi = acos(r) * (1.0 / 3.0);
        // eigenvalues: q + 2p cos(phi + 2k*pi/3); smallest at +2pi/3
        lam = q + 2.0 * p * cos(phi + 2.0943951023931953);
    }

    // Rows of (A - lam*I); eigenvector = best cross product of two rows
    double r0x = a00 - lam, r0y = a01,       r0z = a02;
    double r1x = a01,       r1y = a11 - lam, r1z = a12;
    double r2x = a02,       r2y = a12,       r2z = a22 - lam;

    double c0x = r0y * r1z - r0z * r1y;
    double c0y = r0z * r1x - r0x * r1z;
    double c0z = r0x * r1y - r0y * r1x;

    double c1x = r0y * r2z - r0z * r2y;
    double c1y = r0z * r2x - r0x * r2z;
    double c1z = r0x * r2y - r0y * r2x;

    double c2x = r1y * r2z - r1z * r2y;
    double c2y = r1z * r2x - r1x * r2z;
    double c2z = r1x * r2y - r1y * r2x;

    double n0 = c0x * c0x + c0y * c0y + c0z * c0z;
    double n1 = c1x * c1x + c1y * c1y + c1z * c1z;
    double n2 = c2x * c2x + c2y * c2y + c2z * c2z;

    double vx = c0x, vy = c0y, vz = c0z, nn = n0;
    if (n1 > nn) { vx = c1x; vy = c1y; vz = c1z; nn = n1; }
    if (n2 > nn) { vx = c2x; vy = c2y; vz = c2z; nn = n2; }

    if (nn < 1e-300) { vx = 1.0; vy = 0.0; vz = 0.0; nn = 1.0; }

    double invn = rsqrt(nn);
    out[0] = (float)fabs(vx * invn);
    out[1] = (float)fabs(vy * invn);
    out[2] = (float)fabs(vz * invn);
}

// ---------------------------------------------------------------------------
// Per-thread top-K NN + covariance + normal. sp[j] = (x, y, z, |p_j|^2).
// Ordering key: |p_j|^2 - 2 p_i . p_j  (monotone in true distance for fixed i).
// Heap + index arrays fully unrolled so they live in registers.
// ---------------------------------------------------------------------------
template <int K>
__device__ __forceinline__ void point_normal(
    const float4* __restrict__ sp, int n, int i, float out[3])
{
    const float4 qv = sp[i];
    const float qx = qv.x, qy = qv.y, qz = qv.z;

    float heap[K];
    int   hidx[K];
#pragma unroll
    for (int t = 0; t < K; ++t) { heap[t] = CUDART_INF_F; hidx[t] = 0; }
    float hmax = CUDART_INF_F;

    for (int j = 0; j < n; ++j) {
        float4 c = sp[j];
        float dot = fmaf(qx, c.x, fmaf(qy, c.y, qz * c.z));
        float key = fmaf(-2.0f, dot, c.w);
        if (key < hmax) {
            bool done = false;
#pragma unroll
            for (int t = 0; t < K; ++t) {
                if (!done && heap[t] == hmax) {
                    heap[t] = key; hidx[t] = j; done = true;
                }
            }
            float m = heap[0];
#pragma unroll
            for (int t = 1; t < K; ++t) m = fmaxf(m, heap[t]);
            hmax = m;
        }
    }

    // Covariance of query-centered neighbors (self point contributes zero)
    float xx = 0.f, xy = 0.f, xz = 0.f, yy = 0.f, yz = 0.f, zz = 0.f;
#pragma unroll
    for (int t = 0; t < K; ++t) {
        float4 c = sp[hidx[t]];
        float dx = c.x - qx, dy = c.y - qy, dz = c.z - qz;
        xx = fmaf(dx, dx, xx);
        xy = fmaf(dx, dy, xy);
        xz = fmaf(dx, dz, xz);
        yy = fmaf(dy, dy, yy);
        yz = fmaf(dy, dz, yz);
        zz = fmaf(dz, dz, zz);
    }

    smallest_evec_abs(xx, xy, xz, yy, yz, zz, out);
}

// ---------------------------------------------------------------------------
// Kernel 1: global 32-NN normals. grid = (10, 8), block = 256.
// ---------------------------------------------------------------------------
__global__ void __launch_bounds__(256)
knn_global_kernel(const float* __restrict__ pc)
{
    __shared__ float4 sp[NPTS];   // 40 KB

    const int b = blockIdx.y;
    const float* base = pc + (size_t)b * NPTS * 3;

    for (int j = threadIdx.x; j < NPTS; j += 256) {
        float x = base[3 * j + 0];
        float y = base[3 * j + 1];
        float z = base[3 * j + 2];
        sp[j] = make_float4(x, y, z, fmaf(x, x, fmaf(y, y, z * z)));
    }
    __syncthreads();

    const int i = blockIdx.x * 256 + threadIdx.x;
    if (i < NPTS) {
        float out[3];
        point_normal<K_GLOBAL>(sp, NPTS, i, out);
        const int g = (b * NPTS + i) * 3;
        g_absn_global[g + 0] = out[0];
        g_absn_global[g + 1] = out[1];
        g_absn_global[g + 2] = out[2];
    }
}

// ---------------------------------------------------------------------------
// Kernel 2: patch 16-NN normals. grid = 200 patches, block = 128.
// ---------------------------------------------------------------------------
__global__ void __launch_bounds__(128)
knn_patch_kernel(const float* __restrict__ pc)
{
    __shared__ float4 sp[PATCH_P];

    const int p = blockIdx.x;  // 0..199
    const float* base = pc + (size_t)p * PATCH_P * 3;

    for (int j = threadIdx.x; j < PATCH_P; j += 128) {
        float x = base[3 * j + 0];
        float y = base[3 * j + 1];
        float z = base[3 * j + 2];
        sp[j] = make_float4(x, y, z, fmaf(x, x, fmaf(y, y, z * z)));
    }
    __syncthreads();

    const int l = threadIdx.x;
    if (l < PATCH_P) {
        float out[3];
        point_normal<K_PATCH>(sp, PATCH_P, l, out);
        const int g = (p * PATCH_P + l) * 3;
        g_absn_patch[g + 0] = out[0];
        g_absn_patch[g + 1] = out[1];
        g_absn_patch[g + 2] = out[2];
    }
}

// ---------------------------------------------------------------------------
// Kernel 3: loss = mean ||  |n_patch| - |n_global| ||_2
// ---------------------------------------------------------------------------
__global__ void zero_out_kernel(float* out) { out[0] = 0.0f; }

__global__ void __launch_bounds__(256)
loss_kernel(float* __restrict__ out)
{
    const int i = blockIdx.x * 256 + threadIdx.x;
    float v = 0.0f;
    if (i < TOTAL_PTS) {
        const int g = 3 * i;
        float dx = g_absn_patch[g + 0] - g_absn_global[g + 0];
        float dy = g_absn_patch[g + 1] - g_absn_global[g + 1];
        float dz = g_absn_patch[g + 2] - g_absn_global[g + 2];
        v = sqrtf(fmaf(dx, dx, fmaf(dy, dy, dz * dz)));
    }

    // warp reduce
#pragma unroll
    for (int off = 16; off > 0; off >>= 1)
        v += __shfl_down_sync(0xFFFFFFFFu, v, off);

    __shared__ float warpsum[8];
    const int lane = threadIdx.x & 31;
    const int wid  = threadIdx.x >> 5;
    if (lane == 0) warpsum[wid] = v;
    __syncthreads();

    if (wid == 0) {
        float s = (lane < 8) ? warpsum[lane] : 0.0f;
#pragma unroll
        for (int off = 4; off > 0; off >>= 1)
            s += __shfl_down_sync(0xFFFFFFFFu, s, off);
        if (lane == 0)
            atomicAdd(out, s * (1.0f / (float)TOTAL_PTS));
    }
}

// ---------------------------------------------------------------------------
extern "C" void kernel_launch(void* const* d_in, const int* in_sizes, int n_in,
                              void* d_out, int out_size)
{
    const float* pc = (const float*)d_in[0];   // pointCloud [8,2500,3] f32
    float* out = (float*)d_out;                // [1] f32

    zero_out_kernel<<<1, 1>>>(out);

    dim3 gGrid((NPTS + 255) / 256, BATCH);
    knn_global_kernel<<<gGrid, 256>>>(pc);

    knn_patch_kernel<<<BATCH * NUM_PATCHES, 128>>>(pc);

    loss_kernel<<<(TOTAL_PTS + 255) / 256, 256>>>(out);
}